// round 9
// baseline (speedup 1.0000x reference)
// Round 9: identical resubmission of round 8 (container failure was infra;
// the int32-index candidate never executed).
// edge_index & batch are INT32 on device (harness supports
// float32/int32/bf16 only — int64 inputs are materialized as int32).
// Inputs bound by element count; all graph indices clamped.
#include <cuda_runtime.h>
#include <stdint.h>

#define NN 50000
#define NE 800000
#define NG 64
#define IND 512
#define HIDD 256
#define OUTD 256
#define EPSV 0.1f

__device__ __forceinline__ int clampi(int v, int lo, int hi) {
    return v < lo ? lo : (v > hi ? hi : v);
}

// ---------------- scratch (device globals) ----------------
__device__ __align__(16) int   g_degi[NN];
__device__ __align__(16) int   g_rowstart[NN];
__device__ __align__(16) int   g_fill[NN];
__device__ __align__(16) int   g_csrsrc[NE];
__device__ __align__(16) int   g_perm[NE];
__device__ __align__(16) float g_dinv[NN];
__device__ __align__(16) float g_norm[NE];     // norm in ORIGINAL edge order
__device__ __align__(16) float g_coef[NE];     // coef in CSR order
__device__ __align__(16) float g_al[NN];
__device__ __align__(16) float g_ar[NN];
__device__ __align__(16) float g_h[(size_t)NN * HIDD];
__device__ __align__(16) float g_h0[(size_t)NN * HIDD];
__device__ __align__(16) float g_agg[(size_t)NN * HIDD];
__device__ __align__(16) float g_sums[NG * OUTD];
__device__ __align__(16) float g_cnt[NG];

// ---------------- setup kernels ----------------
__global__ void zeroi_kernel() {
    int i = blockIdx.x * blockDim.x + threadIdx.x;
    if (i < NN) { g_degi[i] = 0; g_fill[i] = 0; }
    if (i < NG * OUTD) g_sums[i] = 0.f;
    if (i < NG) g_cnt[i] = 0.f;
}

__global__ void deg_kernel(const int* __restrict__ ei) {
    int e = blockIdx.x * blockDim.x + threadIdx.x;
    if (e < NE) {
        int d = clampi(ei[NE + e], 0, NN - 1);
        atomicAdd(&g_degi[d], 1);
    }
}

__global__ void dinv_kernel() {
    int i = blockIdx.x * blockDim.x + threadIdx.x;
    if (i < NN) {
        float d = (float)g_degi[i];
        g_dinv[i] = (d > 0.f) ? rsqrtf(fmaxf(d, 1.f)) : 0.f;
    }
}

// single-block exclusive scan over g_degi -> g_rowstart
__global__ void scan_kernel() {
    __shared__ int sh[1024];
    __shared__ int carry_s;
    int tid = threadIdx.x;
    if (tid == 0) carry_s = 0;
    __syncthreads();
    for (int base = 0; base < NN; base += 1024) {
        int v = (base + tid < NN) ? g_degi[base + tid] : 0;
        sh[tid] = v;
        __syncthreads();
        int val = v;
        for (int off = 1; off < 1024; off <<= 1) {
            int t = (tid >= off) ? sh[tid - off] : 0;
            __syncthreads();
            val += t;
            sh[tid] = val;
            __syncthreads();
        }
        int carry = carry_s;
        if (base + tid < NN) g_rowstart[base + tid] = carry + val - v;
        __syncthreads();
        if (tid == 1023) carry_s = carry + val;
        __syncthreads();
    }
}

__global__ void fill_kernel(const int* __restrict__ ei) {
    int e = blockIdx.x * blockDim.x + threadIdx.x;
    if (e < NE) {
        int s = clampi(ei[e], 0, NN - 1);
        int d = clampi(ei[NE + e], 0, NN - 1);
        int pos = g_rowstart[d] + atomicAdd(&g_fill[d], 1);
        pos = clampi(pos, 0, NE - 1);
        g_csrsrc[pos] = s;
        g_perm[e] = pos;
        g_norm[e] = g_dinv[s] * g_dinv[d];
    }
}

// ---------------- per-layer kernels ----------------
// al/ar: one warp per node, dual dot product over HIDD=256.
__global__ void attn_kernel(int sel,
                            const float* __restrict__ alw, const float* __restrict__ alb,
                            const float* __restrict__ arw, const float* __restrict__ arb,
                            int layer) {
    int node = (blockIdx.x * blockDim.x + threadIdx.x) >> 5;
    int lane = threadIdx.x & 31;
    if (node >= NN) return;
    const float* h = sel ? g_agg : g_h;
    const float* hp = h + (size_t)node * HIDD;
    const float* wl = alw + layer * HIDD;
    const float* wr = arw + layer * HIDD;
    float sl = 0.f, sr = 0.f;
#pragma unroll
    for (int i = 0; i < 8; i++) {
        float v = hp[lane + 32 * i];
        sl = fmaf(v, wl[lane + 32 * i], sl);
        sr = fmaf(v, wr[lane + 32 * i], sr);
    }
#pragma unroll
    for (int o = 16; o; o >>= 1) {
        sl += __shfl_xor_sync(0xFFFFFFFFu, sl, o);
        sr += __shfl_xor_sync(0xFFFFFFFFu, sr, o);
    }
    if (lane == 0) {
        g_al[node] = sl + alb[layer];
        g_ar[node] = sr + arb[layer];
    }
}

// coef (CSR order, via perm): coef = norm * tanh(al[src] + ar[dst])
__global__ void coef_kernel(const int* __restrict__ ei) {
    int e = blockIdx.x * blockDim.x + threadIdx.x;
    if (e < NE) {
        int s = clampi(ei[e], 0, NN - 1);
        int d = clampi(ei[NE + e], 0, NN - 1);
        g_coef[g_perm[e]] = g_norm[e] * tanhf(g_al[s] + g_ar[d]);
    }
}

// gather: dst[n] = EPS*h0[n] + sum_{e in row(n)} coef[e]*src[csrsrc[e]]; optional relu.
// sel==0: src=g_h, dst=g_agg.  sel==1: src=g_agg, dst=g_h.
__global__ __launch_bounds__(256) void gather_kernel(int sel, int do_relu)
{
    int node = blockIdx.x * 4 + (threadIdx.x >> 6);
    int c = threadIdx.x & 63;
    if (node >= NN) return;
    const float* h = sel ? g_agg : g_h;
    float* outp    = sel ? g_h   : g_agg;
    int beg = g_rowstart[node];
    int n = g_degi[node];
    float4 acc = ((const float4*)(g_h0 + (size_t)node * HIDD))[c];
    acc.x *= EPSV; acc.y *= EPSV; acc.z *= EPSV; acc.w *= EPSV;
    for (int i = 0; i < n; i++) {
        int s = g_csrsrc[beg + i];
        float cf = g_coef[beg + i];
        float4 v = ((const float4*)(h + (size_t)s * HIDD))[c];
        acc.x = fmaf(cf, v.x, acc.x);
        acc.y = fmaf(cf, v.y, acc.y);
        acc.z = fmaf(cf, v.z, acc.z);
        acc.w = fmaf(cf, v.w, acc.w);
    }
    if (do_relu) {
        acc.x = fmaxf(acc.x, 0.f); acc.y = fmaxf(acc.y, 0.f);
        acc.z = fmaxf(acc.z, 0.f); acc.w = fmaxf(acc.w, 0.f);
    }
    ((float4*)(outp + (size_t)node * HIDD))[c] = acc;
}

// ---------------- SGEMM (fp32, scalar FFMA) ----------------
// CFG==0: A = Aext (x),  C = g_h AND g_h0 (dual store).
// CFG==1: A = g_h,       C = Cext (d_out).
template <int CFG>
__global__ __launch_bounds__(256) void sgemm_kernel(
    const float* __restrict__ Aext, const float* __restrict__ B,
    const float* __restrict__ bias, float* __restrict__ Cext,
    int M, int K, int N)
{
    const float* A = (CFG == 0) ? Aext : (const float*)g_h;
    float* C       = (CFG == 0) ? (float*)g_h : Cext;

    __shared__ float As[8][128];
    __shared__ float Bs[8][128];
    const int tid = threadIdx.x;
    const int row0 = blockIdx.x * 128;
    const int col0 = blockIdx.y * 128;
    const int trow = tid >> 4;
    const int tcol = tid & 15;

    float acc[8][8];
#pragma unroll
    for (int i = 0; i < 8; i++)
#pragma unroll
        for (int j = 0; j < 8; j++) acc[i][j] = 0.f;

    const int arow = tid >> 1;
    const int acol = (tid & 1) << 2;
    const int brow = tid >> 5;
    const int bcol = (tid & 31) << 2;
    const bool avalid = (row0 + arow) < M;
    const float* Ap = A + (size_t)(row0 + arow) * K + acol;
    const float* Bp = B + (size_t)brow * N + col0 + bcol;

    for (int k0 = 0; k0 < K; k0 += 8) {
        float4 av = avalid ? *(const float4*)(Ap + k0) : make_float4(0.f, 0.f, 0.f, 0.f);
        float4 bv = *(const float4*)(Bp + (size_t)k0 * N);
        __syncthreads();
        As[acol + 0][arow] = av.x;
        As[acol + 1][arow] = av.y;
        As[acol + 2][arow] = av.z;
        As[acol + 3][arow] = av.w;
        *(float4*)&Bs[brow][bcol] = bv;
        __syncthreads();
#pragma unroll
        for (int k = 0; k < 8; k++) {
            float a_[8], b_[8];
            *(float4*)(a_)     = *(const float4*)&As[k][trow * 8];
            *(float4*)(a_ + 4) = *(const float4*)&As[k][trow * 8 + 4];
            *(float4*)(b_)     = *(const float4*)&Bs[k][tcol * 8];
            *(float4*)(b_ + 4) = *(const float4*)&Bs[k][tcol * 8 + 4];
#pragma unroll
            for (int i = 0; i < 8; i++)
#pragma unroll
                for (int j = 0; j < 8; j++)
                    acc[i][j] = fmaf(a_[i], b_[j], acc[i][j]);
        }
    }

    float bvals[8];
#pragma unroll
    for (int j = 0; j < 8; j++) bvals[j] = bias[col0 + tcol * 8 + j];

#pragma unroll
    for (int i = 0; i < 8; i++) {
        int r = row0 + trow * 8 + i;
        if (r < M) {
            float o[8];
#pragma unroll
            for (int j = 0; j < 8; j++) o[j] = acc[i][j] + bvals[j];
            float4* cp = (float4*)(C + (size_t)r * N + col0 + tcol * 8);
            cp[0] = make_float4(o[0], o[1], o[2], o[3]);
            cp[1] = make_float4(o[4], o[5], o[6], o[7]);
            if (CFG == 0) {
                float4* cp2 = (float4*)((float*)g_h0 + (size_t)r * N + col0 + tcol * 8);
                cp2[0] = make_float4(o[0], o[1], o[2], o[3]);
                cp2[1] = make_float4(o[4], o[5], o[6], o[7]);
            }
        }
    }
}

// ---------------- pooling (batch is sorted: strip accumulation) ----------------
#define STRIP 200
__global__ __launch_bounds__(256) void pool_kernel(
    const float* __restrict__ nr, const int* __restrict__ batch)
{
    int c = threadIdx.x;                      // 0..255 column
    int n0 = blockIdx.x * STRIP;
    int n1 = min(n0 + STRIP, NN);
    if (n0 >= NN) return;
    int curg = clampi(batch[n0], 0, NG - 1);
    float acc = 0.f;
    int cnt_local = 0;
    for (int n = n0; n < n1; n++) {
        int g = clampi(batch[n], 0, NG - 1);
        if (g != curg) {
            atomicAdd(&g_sums[curg * OUTD + c], acc);
            if (c == 0) atomicAdd(&g_cnt[curg], (float)cnt_local);
            acc = 0.f; cnt_local = 0; curg = g;
        }
        acc += nr[(size_t)n * OUTD + c];
        cnt_local++;
    }
    atomicAdd(&g_sums[curg * OUTD + c], acc);
    if (c == 0) atomicAdd(&g_cnt[curg], (float)cnt_local);
}

__global__ void finalize_kernel(float* __restrict__ out) {
    int i = blockIdx.x * blockDim.x + threadIdx.x;
    if (i < NG * OUTD) out[i] = g_sums[i] / fmaxf(g_cnt[i >> 8], 1.0f);
}

// ---------------- launch: inputs bound BY SIZE, kernel launches only ----------------
extern "C" void kernel_launch(void* const* d_in, const int* in_sizes, int n_in,
                              void* d_out, int out_size) {
    const float *x = 0, *W_in = 0, *b_in = 0, *alw = 0, *alb = 0,
                *arw = 0, *arb = 0, *W_out = 0, *b_out = 0;
    const int *ei = 0, *batch = 0;
    for (int i = 0; i < n_in; i++) {
        long long s = in_sizes[i];
        const void* p = d_in[i];
        switch (s) {
            case 25600000LL: x     = (const float*)p; break;           // 50000*512
            case 1600000LL:  ei    = (const int*)p;   break;           // 2*800000 (int32)
            case 50000LL:    batch = (const int*)p;   break;           // int32
            case 131072LL:   W_in  = (const float*)p; break;           // 512*256
            case 65536LL:    W_out = (const float*)p; break;           // 256*256
            case 512LL:      if (!alw) alw = (const float*)p; else arw = (const float*)p; break;
            case 2LL:        if (!alb) alb = (const float*)p; else arb = (const float*)p; break;
            case 256LL:      if (!b_in) b_in = (const float*)p; else b_out = (const float*)p; break;
            default: break;
        }
    }
    float* out = (float*)d_out;

    const int T = 256;

    // setup: zero, degree, dinv, scan, fill (CSR + norm)
    zeroi_kernel<<<(NN + T - 1) / T, T>>>();
    deg_kernel<<<(NE + T - 1) / T, T>>>(ei);
    dinv_kernel<<<(NN + T - 1) / T, T>>>();
    scan_kernel<<<1, 1024>>>();
    fill_kernel<<<(NE + T - 1) / T, T>>>(ei);

    // input GEMM: g_h = g_h0 = x @ W_in + b_in
    dim3 g1((NN + 127) / 128, HIDD / 128);
    sgemm_kernel<0><<<g1, 256>>>(x, W_in, b_in, nullptr, NN, IND, HIDD);

    // layer 0: g_h -> g_agg (relu fused)
    attn_kernel<<<(NN + 7) / 8, T>>>(0, alw, alb, arw, arb, 0);
    coef_kernel<<<(NE + T - 1) / T, T>>>(ei);
    gather_kernel<<<(NN + 3) / 4, 256>>>(0, 1);

    // layer 1: g_agg -> g_h (no relu)
    attn_kernel<<<(NN + 7) / 8, T>>>(1, alw, alb, arw, arb, 1);
    coef_kernel<<<(NE + T - 1) / T, T>>>(ei);
    gather_kernel<<<(NN + 3) / 4, 256>>>(1, 0);

    // output GEMM: node_repr = g_h @ W_out + b_out -> d_out
    dim3 g2((NN + 127) / 128, OUTD / 128);
    sgemm_kernel<1><<<g2, 256>>>(nullptr, W_out, b_out, out, NN, HIDD, OUTD);

    // mean pool over sorted batch
    pool_kernel<<<(NN + STRIP - 1) / STRIP, 256>>>(out, batch);
    finalize_kernel<<<(NG * OUTD + T - 1) / T, T>>>(out + (size_t)NN * OUTD);
}

// round 10
// speedup vs baseline: 1.2352x; 1.2352x over previous
// Round 10: (a) tf32 tensor-core GEMM with 3xTF32 compensation replaces
// scalar-FFMA sgemm; (b) fast warp-shuffle scan replaces barrier-heavy scan.
// Index binding (int32, by-size) unchanged from the passing round 9.
#include <cuda_runtime.h>
#include <stdint.h>

#define NN 50000
#define NE 800000
#define NG 64
#define IND 512
#define HIDD 256
#define OUTD 256
#define EPSV 0.1f

__device__ __forceinline__ int clampi(int v, int lo, int hi) {
    return v < lo ? lo : (v > hi ? hi : v);
}

// ---------------- scratch (device globals) ----------------
__device__ __align__(16) int   g_degi[NN];
__device__ __align__(16) int   g_rowstart[NN];
__device__ __align__(16) int   g_fill[NN];
__device__ __align__(16) int   g_csrsrc[NE];
__device__ __align__(16) int   g_perm[NE];
__device__ __align__(16) float g_dinv[NN];
__device__ __align__(16) float g_norm[NE];
__device__ __align__(16) float g_coef[NE];
__device__ __align__(16) float g_al[NN];
__device__ __align__(16) float g_ar[NN];
__device__ __align__(16) float g_h[(size_t)NN * HIDD];
__device__ __align__(16) float g_h0[(size_t)NN * HIDD];
__device__ __align__(16) float g_agg[(size_t)NN * HIDD];
__device__ __align__(16) float g_sums[NG * OUTD];
__device__ __align__(16) float g_cnt[NG];

// ---------------- setup kernels ----------------
__global__ void zeroi_kernel() {
    int i = blockIdx.x * blockDim.x + threadIdx.x;
    if (i < NN) { g_degi[i] = 0; g_fill[i] = 0; }
    if (i < NG * OUTD) g_sums[i] = 0.f;
    if (i < NG) g_cnt[i] = 0.f;
}

__global__ void deg_kernel(const int* __restrict__ ei) {
    int e = blockIdx.x * blockDim.x + threadIdx.x;
    if (e < NE) {
        int d = clampi(ei[NE + e], 0, NN - 1);
        atomicAdd(&g_degi[d], 1);
    }
}

__global__ void dinv_kernel() {
    int i = blockIdx.x * blockDim.x + threadIdx.x;
    if (i < NN) {
        float d = (float)g_degi[i];
        g_dinv[i] = (d > 0.f) ? rsqrtf(fmaxf(d, 1.f)) : 0.f;
    }
}

// fast exclusive scan: serial per-thread chunk + warp-shuffle block scan (2 barriers)
__global__ void scan_kernel() {
    const int CH = (NN + 1023) / 1024;   // 49
    int tid = threadIdx.x;
    int lane = tid & 31, w = tid >> 5;
    int start = tid * CH;
    int end = min(start + CH, NN);
    int sum = 0;
    for (int i = start; i < end; i++) sum += g_degi[i];
    // inclusive warp scan of sums
    int incl = sum;
#pragma unroll
    for (int o = 1; o < 32; o <<= 1) {
        int t = __shfl_up_sync(0xFFFFFFFFu, incl, o);
        if (lane >= o) incl += t;
    }
    __shared__ int wsum[32];
    if (lane == 31) wsum[w] = incl;
    __syncthreads();
    if (w == 0) {
        int x = wsum[lane];
        int xi = x;
#pragma unroll
        for (int o = 1; o < 32; o <<= 1) {
            int t = __shfl_up_sync(0xFFFFFFFFu, xi, o);
            if (lane >= o) xi += t;
        }
        wsum[lane] = xi - x;   // exclusive warp offsets
    }
    __syncthreads();
    int run = wsum[w] + incl - sum;   // exclusive prefix for this thread's chunk
    for (int i = start; i < end; i++) {
        g_rowstart[i] = run;
        run += g_degi[i];
    }
}

__global__ void fill_kernel(const int* __restrict__ ei) {
    int e = blockIdx.x * blockDim.x + threadIdx.x;
    if (e < NE) {
        int s = clampi(ei[e], 0, NN - 1);
        int d = clampi(ei[NE + e], 0, NN - 1);
        int pos = g_rowstart[d] + atomicAdd(&g_fill[d], 1);
        pos = clampi(pos, 0, NE - 1);
        g_csrsrc[pos] = s;
        g_perm[e] = pos;
        g_norm[e] = g_dinv[s] * g_dinv[d];
    }
}

// ---------------- per-layer kernels ----------------
__global__ void attn_kernel(int sel,
                            const float* __restrict__ alw, const float* __restrict__ alb,
                            const float* __restrict__ arw, const float* __restrict__ arb,
                            int layer) {
    int node = (blockIdx.x * blockDim.x + threadIdx.x) >> 5;
    int lane = threadIdx.x & 31;
    if (node >= NN) return;
    const float* h = sel ? g_agg : g_h;
    const float* hp = h + (size_t)node * HIDD;
    const float* wl = alw + layer * HIDD;
    const float* wr = arw + layer * HIDD;
    float sl = 0.f, sr = 0.f;
#pragma unroll
    for (int i = 0; i < 8; i++) {
        float v = hp[lane + 32 * i];
        sl = fmaf(v, wl[lane + 32 * i], sl);
        sr = fmaf(v, wr[lane + 32 * i], sr);
    }
#pragma unroll
    for (int o = 16; o; o >>= 1) {
        sl += __shfl_xor_sync(0xFFFFFFFFu, sl, o);
        sr += __shfl_xor_sync(0xFFFFFFFFu, sr, o);
    }
    if (lane == 0) {
        g_al[node] = sl + alb[layer];
        g_ar[node] = sr + arb[layer];
    }
}

__global__ void coef_kernel(const int* __restrict__ ei) {
    int e = blockIdx.x * blockDim.x + threadIdx.x;
    if (e < NE) {
        int s = clampi(ei[e], 0, NN - 1);
        int d = clampi(ei[NE + e], 0, NN - 1);
        g_coef[g_perm[e]] = g_norm[e] * tanhf(g_al[s] + g_ar[d]);
    }
}

__global__ __launch_bounds__(256) void gather_kernel(int sel, int do_relu)
{
    int node = blockIdx.x * 4 + (threadIdx.x >> 6);
    int c = threadIdx.x & 63;
    if (node >= NN) return;
    const float* h = sel ? g_agg : g_h;
    float* outp    = sel ? g_h   : g_agg;
    int beg = g_rowstart[node];
    int n = g_degi[node];
    float4 acc = ((const float4*)(g_h0 + (size_t)node * HIDD))[c];
    acc.x *= EPSV; acc.y *= EPSV; acc.z *= EPSV; acc.w *= EPSV;
    for (int i = 0; i < n; i++) {
        int s = g_csrsrc[beg + i];
        float cf = g_coef[beg + i];
        float4 v = ((const float4*)(h + (size_t)s * HIDD))[c];
        acc.x = fmaf(cf, v.x, acc.x);
        acc.y = fmaf(cf, v.y, acc.y);
        acc.z = fmaf(cf, v.z, acc.z);
        acc.w = fmaf(cf, v.w, acc.w);
    }
    if (do_relu) {
        acc.x = fmaxf(acc.x, 0.f); acc.y = fmaxf(acc.y, 0.f);
        acc.z = fmaxf(acc.z, 0.f); acc.w = fmaxf(acc.w, 0.f);
    }
    ((float4*)(outp + (size_t)node * HIDD))[c] = acc;
}

// ---------------- tf32 tensor-core GEMM (3xTF32 compensation) ----------------
__device__ __forceinline__ unsigned f2tf32(float v) {
    unsigned r;
    asm("cvt.rna.tf32.f32 %0, %1;" : "=r"(r) : "f"(v));
    return r;
}
__device__ __forceinline__ void split_tf32(float v, unsigned& big, unsigned& sml) {
    big = f2tf32(v);
    sml = f2tf32(v - __uint_as_float(big));
}
__device__ __forceinline__ void mma_tf32(float* c, const unsigned* a, const unsigned* b) {
    asm volatile(
        "mma.sync.aligned.m16n8k8.row.col.f32.tf32.tf32.f32 "
        "{%0,%1,%2,%3}, {%4,%5,%6,%7}, {%8,%9}, {%0,%1,%2,%3};"
        : "+f"(c[0]), "+f"(c[1]), "+f"(c[2]), "+f"(c[3])
        : "r"(a[0]), "r"(a[1]), "r"(a[2]), "r"(a[3]), "r"(b[0]), "r"(b[1]));
}

// C[M,N] = A[M,K]@B[K,N] + bias.  CFG==0: A=Aext(x), C=g_h AND g_h0.
//                                 CFG==1: A=g_h,     C=Cext(d_out).
// BM=128, BN=64, BK=16. 256 threads = 8 warps (4 M x 2 N), warp tile 32x32.
template <int CFG>
__global__ __launch_bounds__(256) void tfgemm_kernel(
    const float* __restrict__ Aext, const float* __restrict__ B,
    const float* __restrict__ bias, float* __restrict__ Cext,
    int M, int K, int N)
{
    const float* A = (CFG == 0) ? Aext : (const float*)g_h;
    float* C       = (CFG == 0) ? (float*)g_h : Cext;

    __shared__ float As[128][20];   // stride 20: conflict-free fragment reads
    __shared__ float Bs[16][72];    // stride 72: conflict-free fragment reads

    const int tid  = threadIdx.x;
    const int lane = tid & 31;
    const int warp = tid >> 5;
    const int wm = warp >> 1;          // 0..3
    const int wn = warp & 1;           // 0..1
    const int g   = lane >> 2;         // 0..7
    const int tig = lane & 3;          // 0..3
    const int row0 = blockIdx.x * 128;
    const int col0 = blockIdx.y * 64;
    const int rw = wm * 32;            // warp row offset in tile
    const int cw = wn * 32;            // warp col offset in tile

    float acc[2][4][4];
#pragma unroll
    for (int mt = 0; mt < 2; mt++)
#pragma unroll
        for (int nt = 0; nt < 4; nt++)
#pragma unroll
            for (int r = 0; r < 4; r++) acc[mt][nt][r] = 0.f;

    // staging indices
    const int r_a  = tid >> 2;           // 0..63 (and +64)
    const int kq_a = tid & 3;            // 0..3  -> k offset kq*4
    const int r_b  = tid >> 4;           // 0..15
    const int cq_b = tid & 15;           // 0..15 -> col offset cq*4
    const bool va0 = (row0 + r_a) < M;
    const bool va1 = (row0 + r_a + 64) < M;

    const int KT = K >> 4;
    float4 pa0, pa1, pb;
    {   // preload first tile
        pa0 = va0 ? *(const float4*)(A + (size_t)(row0 + r_a) * K + kq_a * 4)
                  : make_float4(0.f, 0.f, 0.f, 0.f);
        pa1 = va1 ? *(const float4*)(A + (size_t)(row0 + r_a + 64) * K + kq_a * 4)
                  : make_float4(0.f, 0.f, 0.f, 0.f);
        pb  = *(const float4*)(B + (size_t)r_b * N + col0 + cq_b * 4);
    }

    for (int kt = 0; kt < KT; kt++) {
        // store staged tile
        *(float4*)&As[r_a][kq_a * 4]      = pa0;
        *(float4*)&As[r_a + 64][kq_a * 4] = pa1;
        *(float4*)&Bs[r_b][cq_b * 4]      = pb;
        __syncthreads();

        // prefetch next tile into registers (overlaps with mma)
        if (kt + 1 < KT) {
            int k0n = (kt + 1) * 16;
            pa0 = va0 ? *(const float4*)(A + (size_t)(row0 + r_a) * K + k0n + kq_a * 4)
                      : make_float4(0.f, 0.f, 0.f, 0.f);
            pa1 = va1 ? *(const float4*)(A + (size_t)(row0 + r_a + 64) * K + k0n + kq_a * 4)
                      : make_float4(0.f, 0.f, 0.f, 0.f);
            pb  = *(const float4*)(B + (size_t)(k0n + r_b) * N + col0 + cq_b * 4);
        }

#pragma unroll
        for (int ks = 0; ks < 16; ks += 8) {
            unsigned abig[2][4], asml[2][4];
#pragma unroll
            for (int mt = 0; mt < 2; mt++) {
                int rbase = rw + mt * 16;
                float v0 = As[rbase + g][ks + tig];
                float v1 = As[rbase + g + 8][ks + tig];
                float v2 = As[rbase + g][ks + tig + 4];
                float v3 = As[rbase + g + 8][ks + tig + 4];
                split_tf32(v0, abig[mt][0], asml[mt][0]);
                split_tf32(v1, abig[mt][1], asml[mt][1]);
                split_tf32(v2, abig[mt][2], asml[mt][2]);
                split_tf32(v3, abig[mt][3], asml[mt][3]);
            }
            unsigned bbig[4][2], bsml[4][2];
#pragma unroll
            for (int nt = 0; nt < 4; nt++) {
                int cbase = cw + nt * 8;
                float w0 = Bs[ks + tig][cbase + g];
                float w1 = Bs[ks + tig + 4][cbase + g];
                split_tf32(w0, bbig[nt][0], bsml[nt][0]);
                split_tf32(w1, bbig[nt][1], bsml[nt][1]);
            }
#pragma unroll
            for (int mt = 0; mt < 2; mt++)
#pragma unroll
                for (int nt = 0; nt < 4; nt++) {
                    mma_tf32(acc[mt][nt], abig[mt], bbig[nt]);
                    mma_tf32(acc[mt][nt], abig[mt], bsml[nt]);
                    mma_tf32(acc[mt][nt], asml[mt], bbig[nt]);
                }
        }
        __syncthreads();
    }

    // epilogue: bias add + store (dual store for CFG==0)
#pragma unroll
    for (int nt = 0; nt < 4; nt++) {
        int ccol = col0 + cw + nt * 8 + 2 * tig;
        float2 bb = *(const float2*)&bias[ccol];
#pragma unroll
        for (int mt = 0; mt < 2; mt++) {
            int r1 = row0 + rw + mt * 16 + g;
            int r2 = r1 + 8;
            float2 o0 = make_float2(acc[mt][nt][0] + bb.x, acc[mt][nt][1] + bb.y);
            float2 o1 = make_float2(acc[mt][nt][2] + bb.x, acc[mt][nt][3] + bb.y);
            if (r1 < M) {
                *(float2*)(C + (size_t)r1 * N + ccol) = o0;
                if (CFG == 0) *(float2*)((float*)g_h0 + (size_t)r1 * N + ccol) = o0;
            }
            if (r2 < M) {
                *(float2*)(C + (size_t)r2 * N + ccol) = o1;
                if (CFG == 0) *(float2*)((float*)g_h0 + (size_t)r2 * N + ccol) = o1;
            }
        }
    }
}

// ---------------- pooling ----------------
#define STRIP 200
__global__ __launch_bounds__(256) void pool_kernel(
    const float* __restrict__ nr, const int* __restrict__ batch)
{
    int c = threadIdx.x;
    int n0 = blockIdx.x * STRIP;
    int n1 = min(n0 + STRIP, NN);
    if (n0 >= NN) return;
    int curg = clampi(batch[n0], 0, NG - 1);
    float acc = 0.f;
    int cnt_local = 0;
    for (int n = n0; n < n1; n++) {
        int g = clampi(batch[n], 0, NG - 1);
        if (g != curg) {
            atomicAdd(&g_sums[curg * OUTD + c], acc);
            if (c == 0) atomicAdd(&g_cnt[curg], (float)cnt_local);
            acc = 0.f; cnt_local = 0; curg = g;
        }
        acc += nr[(size_t)n * OUTD + c];
        cnt_local++;
    }
    atomicAdd(&g_sums[curg * OUTD + c], acc);
    if (c == 0) atomicAdd(&g_cnt[curg], (float)cnt_local);
}

__global__ void finalize_kernel(float* __restrict__ out) {
    int i = blockIdx.x * blockDim.x + threadIdx.x;
    if (i < NG * OUTD) out[i] = g_sums[i] / fmaxf(g_cnt[i >> 8], 1.0f);
}

// ---------------- launch ----------------
extern "C" void kernel_launch(void* const* d_in, const int* in_sizes, int n_in,
                              void* d_out, int out_size) {
    const float *x = 0, *W_in = 0, *b_in = 0, *alw = 0, *alb = 0,
                *arw = 0, *arb = 0, *W_out = 0, *b_out = 0;
    const int *ei = 0, *batch = 0;
    for (int i = 0; i < n_in; i++) {
        long long s = in_sizes[i];
        const void* p = d_in[i];
        switch (s) {
            case 25600000LL: x     = (const float*)p; break;
            case 1600000LL:  ei    = (const int*)p;   break;
            case 50000LL:    batch = (const int*)p;   break;
            case 131072LL:   W_in  = (const float*)p; break;
            case 65536LL:    W_out = (const float*)p; break;
            case 512LL:      if (!alw) alw = (const float*)p; else arw = (const float*)p; break;
            case 2LL:        if (!alb) alb = (const float*)p; else arb = (const float*)p; break;
            case 256LL:      if (!b_in) b_in = (const float*)p; else b_out = (const float*)p; break;
            default: break;
        }
    }
    float* out = (float*)d_out;

    const int T = 256;

    zeroi_kernel<<<(NN + T - 1) / T, T>>>();
    deg_kernel<<<(NE + T - 1) / T, T>>>(ei);
    dinv_kernel<<<(NN + T - 1) / T, T>>>();
    scan_kernel<<<1, 1024>>>();
    fill_kernel<<<(NE + T - 1) / T, T>>>(ei);

    // input GEMM: g_h = g_h0 = x @ W_in + b_in
    dim3 g1((NN + 127) / 128, HIDD / 64);
    tfgemm_kernel<0><<<g1, 256>>>(x, W_in, b_in, nullptr, NN, IND, HIDD);

    // layer 0: g_h -> g_agg (relu fused)
    attn_kernel<<<(NN + 7) / 8, T>>>(0, alw, alb, arw, arb, 0);
    coef_kernel<<<(NE + T - 1) / T, T>>>(ei);
    gather_kernel<<<(NN + 3) / 4, 256>>>(0, 1);

    // layer 1: g_agg -> g_h (no relu)
    attn_kernel<<<(NN + 7) / 8, T>>>(1, alw, alb, arw, arb, 1);
    coef_kernel<<<(NE + T - 1) / T, T>>>(ei);
    gather_kernel<<<(NN + 3) / 4, 256>>>(1, 0);

    // output GEMM: node_repr = g_h @ W_out + b_out -> d_out
    dim3 g2((NN + 127) / 128, OUTD / 64);
    tfgemm_kernel<1><<<g2, 256>>>(nullptr, W_out, b_out, out, NN, HIDD, OUTD);

    // mean pool over sorted batch
    pool_kernel<<<(NN + STRIP - 1) / STRIP, 256>>>(out, batch);
    finalize_kernel<<<(NG * OUTD + T - 1) / T, T>>>(out + (size_t)NN * OUTD);
}

// round 12
// speedup vs baseline: 1.5709x; 1.2717x over previous
// Round 12: identical resubmission of round 11 (container failure was infra;
// the bf16-3-term + 3-phase-scan candidate never executed).
// (a) multi-block 3-phase scan replaces 48µs single-block scan;
// (b) GEMM is bf16 3-term (m16n8k16), operand split done ONCE at smem staging.
#include <cuda_runtime.h>
#include <stdint.h>

#define NN 50000
#define NE 800000
#define NG 64
#define IND 512
#define HIDD 256
#define OUTD 256
#define EPSV 0.1f

typedef unsigned int u32;

__device__ __forceinline__ int clampi(int v, int lo, int hi) {
    return v < lo ? lo : (v > hi ? hi : v);
}

// ---------------- scratch (device globals) ----------------
__device__ __align__(16) int   g_degi[NN];
__device__ __align__(16) int   g_rowstart[NN];
__device__ __align__(16) int   g_fill[NN];
__device__ __align__(16) int   g_bsum[64];
__device__ __align__(16) int   g_boff[64];
__device__ __align__(16) int   g_csrsrc[NE];
__device__ __align__(16) int   g_perm[NE];
__device__ __align__(16) float g_dinv[NN];
__device__ __align__(16) float g_norm[NE];
__device__ __align__(16) float g_coef[NE];
__device__ __align__(16) float g_al[NN];
__device__ __align__(16) float g_ar[NN];
__device__ __align__(16) float g_h[(size_t)NN * HIDD];
__device__ __align__(16) float g_h0[(size_t)NN * HIDD];
__device__ __align__(16) float g_agg[(size_t)NN * HIDD];
__device__ __align__(16) float g_sums[NG * OUTD];
__device__ __align__(16) float g_cnt[NG];

// ---------------- setup kernels ----------------
__global__ void zeroi_kernel() {
    int i = blockIdx.x * blockDim.x + threadIdx.x;
    if (i < NN) { g_degi[i] = 0; g_fill[i] = 0; }
    if (i < NG * OUTD) g_sums[i] = 0.f;
    if (i < NG) g_cnt[i] = 0.f;
}

__global__ void deg_kernel(const int* __restrict__ ei) {
    int e = blockIdx.x * blockDim.x + threadIdx.x;
    if (e < NE) {
        int d = clampi(ei[NE + e], 0, NN - 1);
        atomicAdd(&g_degi[d], 1);
    }
}

__global__ void dinv_kernel() {
    int i = blockIdx.x * blockDim.x + threadIdx.x;
    if (i < NN) {
        float d = (float)g_degi[i];
        g_dinv[i] = (d > 0.f) ? rsqrtf(fmaxf(d, 1.f)) : 0.f;
    }
}

// 3-phase scan: A) per-block exclusive scan + block sums, B) scan block sums, C) add offsets
__global__ void scanA_kernel() {
    int tid = threadIdx.x;
    int i = blockIdx.x * 1024 + tid;
    int lane = tid & 31, w = tid >> 5;
    int v = (i < NN) ? g_degi[i] : 0;
    int incl = v;
#pragma unroll
    for (int o = 1; o < 32; o <<= 1) {
        int t = __shfl_up_sync(0xFFFFFFFFu, incl, o);
        if (lane >= o) incl += t;
    }
    __shared__ int wsum[32];
    if (lane == 31) wsum[w] = incl;
    __syncthreads();
    if (w == 0) {
        int x = wsum[lane];
        int xi = x;
#pragma unroll
        for (int o = 1; o < 32; o <<= 1) {
            int t = __shfl_up_sync(0xFFFFFFFFu, xi, o);
            if (lane >= o) xi += t;
        }
        wsum[lane] = xi;   // inclusive warp sums
    }
    __syncthreads();
    int woff = (w > 0) ? wsum[w - 1] : 0;
    if (i < NN) g_rowstart[i] = woff + incl - v;
    if (tid == 1023) g_bsum[blockIdx.x] = wsum[31];
}

__global__ void scanB_kernel(int nblocks) {
    int tid = threadIdx.x;          // 64 threads
    int lane = tid & 31, w = tid >> 5;
    int v = (tid < nblocks) ? g_bsum[tid] : 0;
    int incl = v;
#pragma unroll
    for (int o = 1; o < 32; o <<= 1) {
        int t = __shfl_up_sync(0xFFFFFFFFu, incl, o);
        if (lane >= o) incl += t;
    }
    __shared__ int ws[2];
    if (lane == 31) ws[w] = incl;
    __syncthreads();
    int off = (w == 1) ? ws[0] : 0;
    if (tid < nblocks) g_boff[tid] = off + incl - v;
}

__global__ void scanC_kernel() {
    int i = blockIdx.x * 1024 + threadIdx.x;
    if (i < NN) g_rowstart[i] += g_boff[blockIdx.x];
}

__global__ void fill_kernel(const int* __restrict__ ei) {
    int e = blockIdx.x * blockDim.x + threadIdx.x;
    if (e < NE) {
        int s = clampi(ei[e], 0, NN - 1);
        int d = clampi(ei[NE + e], 0, NN - 1);
        int pos = g_rowstart[d] + atomicAdd(&g_fill[d], 1);
        pos = clampi(pos, 0, NE - 1);
        g_csrsrc[pos] = s;
        g_perm[e] = pos;
        g_norm[e] = g_dinv[s] * g_dinv[d];
    }
}

// ---------------- per-layer kernels ----------------
__global__ void attn_kernel(int sel,
                            const float* __restrict__ alw, const float* __restrict__ alb,
                            const float* __restrict__ arw, const float* __restrict__ arb,
                            int layer) {
    int node = (blockIdx.x * blockDim.x + threadIdx.x) >> 5;
    int lane = threadIdx.x & 31;
    if (node >= NN) return;
    const float* h = sel ? g_agg : g_h;
    const float* hp = h + (size_t)node * HIDD;
    const float* wl = alw + layer * HIDD;
    const float* wr = arw + layer * HIDD;
    float sl = 0.f, sr = 0.f;
#pragma unroll
    for (int i = 0; i < 8; i++) {
        float v = hp[lane + 32 * i];
        sl = fmaf(v, wl[lane + 32 * i], sl);
        sr = fmaf(v, wr[lane + 32 * i], sr);
    }
#pragma unroll
    for (int o = 16; o; o >>= 1) {
        sl += __shfl_xor_sync(0xFFFFFFFFu, sl, o);
        sr += __shfl_xor_sync(0xFFFFFFFFu, sr, o);
    }
    if (lane == 0) {
        g_al[node] = sl + alb[layer];
        g_ar[node] = sr + arb[layer];
    }
}

__global__ void coef_kernel(const int* __restrict__ ei) {
    int e = blockIdx.x * blockDim.x + threadIdx.x;
    if (e < NE) {
        int s = clampi(ei[e], 0, NN - 1);
        int d = clampi(ei[NE + e], 0, NN - 1);
        g_coef[g_perm[e]] = g_norm[e] * tanhf(g_al[s] + g_ar[d]);
    }
}

__global__ __launch_bounds__(256) void gather_kernel(int sel, int do_relu)
{
    int node = blockIdx.x * 4 + (threadIdx.x >> 6);
    int c = threadIdx.x & 63;
    if (node >= NN) return;
    const float* h = sel ? g_agg : g_h;
    float* outp    = sel ? g_h   : g_agg;
    int beg = g_rowstart[node];
    int n = g_degi[node];
    float4 acc = ((const float4*)(g_h0 + (size_t)node * HIDD))[c];
    acc.x *= EPSV; acc.y *= EPSV; acc.z *= EPSV; acc.w *= EPSV;
    for (int i = 0; i < n; i++) {
        int s = g_csrsrc[beg + i];
        float cf = g_coef[beg + i];
        float4 v = ((const float4*)(h + (size_t)s * HIDD))[c];
        acc.x = fmaf(cf, v.x, acc.x);
        acc.y = fmaf(cf, v.y, acc.y);
        acc.z = fmaf(cf, v.z, acc.z);
        acc.w = fmaf(cf, v.w, acc.w);
    }
    if (do_relu) {
        acc.x = fmaxf(acc.x, 0.f); acc.y = fmaxf(acc.y, 0.f);
        acc.z = fmaxf(acc.z, 0.f); acc.w = fmaxf(acc.w, 0.f);
    }
    ((float4*)(outp + (size_t)node * HIDD))[c] = acc;
}

// ---------------- bf16 3-term tensor-core GEMM ----------------
__device__ __forceinline__ u32 cvt_bf2(float lo, float hi) {
    u32 d;
    asm("cvt.rn.bf16x2.f32 %0, %1, %2;" : "=r"(d) : "f"(hi), "f"(lo));
    return d;
}
// split (lo,hi) floats into packed big/small bf16x2
__device__ __forceinline__ void split2(float lo, float hi, u32& big, u32& sml) {
    big = cvt_bf2(lo, hi);
    float blo = __uint_as_float(big << 16);
    float bhi = __uint_as_float(big & 0xFFFF0000u);
    sml = cvt_bf2(lo - blo, hi - bhi);
}
__device__ __forceinline__ void mma_bf16(float* c, const u32* a, const u32* b) {
    asm volatile(
        "mma.sync.aligned.m16n8k16.row.col.f32.bf16.bf16.f32 "
        "{%0,%1,%2,%3}, {%4,%5,%6,%7}, {%8,%9}, {%0,%1,%2,%3};"
        : "+f"(c[0]), "+f"(c[1]), "+f"(c[2]), "+f"(c[3])
        : "r"(a[0]), "r"(a[1]), "r"(a[2]), "r"(a[3]), "r"(b[0]), "r"(b[1]));
}

// C[M,N] = A[M,K]@B[K,N] + bias.  CFG==0: A=Aext(x), C=g_h AND g_h0.
//                                 CFG==1: A=g_h,     C=Cext(d_out).
// BM=128, BN=64, BK=16. 256 threads = 8 warps (4 M x 2 N), warp tile 32x32.
template <int CFG>
__global__ __launch_bounds__(256) void bfgemm_kernel(
    const float* __restrict__ Aext, const float* __restrict__ B,
    const float* __restrict__ bias, float* __restrict__ Cext,
    int M, int K, int N)
{
    const float* A = (CFG == 0) ? Aext : (const float*)g_h;
    float* C       = (CFG == 0) ? (float*)g_h : Cext;

    __shared__ u32 Abig[128][20], Asml[128][20];   // cols 0..7 used (8 k-pairs)
    __shared__ u32 Bbig[8][72],  Bsml[8][72];      // [k-pair][n], cols 0..63 used

    const int tid  = threadIdx.x;
    const int lane = tid & 31;
    const int warp = tid >> 5;
    const int wm = warp >> 1;
    const int wn = warp & 1;
    const int g   = lane >> 2;
    const int tig = lane & 3;
    const int row0 = blockIdx.x * 128;
    const int col0 = blockIdx.y * 64;
    const int rw = wm * 32;
    const int cw = wn * 32;

    float acc[2][4][4];
#pragma unroll
    for (int mt = 0; mt < 2; mt++)
#pragma unroll
        for (int nt = 0; nt < 4; nt++)
#pragma unroll
            for (int r = 0; r < 4; r++) acc[mt][nt][r] = 0.f;

    // A staging: 256 threads, rows r_a & r_a+64, k floats 4kq..4kq+3
    const int r_a  = tid >> 2;
    const int kq_a = tid & 3;
    const bool va0 = (row0 + r_a) < M;
    const bool va1 = (row0 + r_a + 64) < M;
    // B staging: threads 0..127: k-pair p (rows 2p,2p+1), n cols 4nq..4nq+3
    const int p_b  = tid >> 4;          // 0..7 (tid<128)
    const int nq_b = tid & 15;

    const int KT = K >> 4;
    float4 pa0, pa1, pb0, pb1;
    {
        pa0 = va0 ? *(const float4*)(A + (size_t)(row0 + r_a) * K + kq_a * 4)
                  : make_float4(0.f, 0.f, 0.f, 0.f);
        pa1 = va1 ? *(const float4*)(A + (size_t)(row0 + r_a + 64) * K + kq_a * 4)
                  : make_float4(0.f, 0.f, 0.f, 0.f);
        if (tid < 128) {
            pb0 = *(const float4*)(B + (size_t)(2 * p_b) * N + col0 + nq_b * 4);
            pb1 = *(const float4*)(B + (size_t)(2 * p_b + 1) * N + col0 + nq_b * 4);
        }
    }

    for (int kt = 0; kt < KT; kt++) {
        // stage with on-the-fly split (once per element)
        {
            u32 b0, s0, b1, s1;
            split2(pa0.x, pa0.y, b0, s0);
            split2(pa0.z, pa0.w, b1, s1);
            Abig[r_a][2 * kq_a] = b0;  Abig[r_a][2 * kq_a + 1] = b1;
            Asml[r_a][2 * kq_a] = s0;  Asml[r_a][2 * kq_a + 1] = s1;
            split2(pa1.x, pa1.y, b0, s0);
            split2(pa1.z, pa1.w, b1, s1);
            Abig[r_a + 64][2 * kq_a] = b0;  Abig[r_a + 64][2 * kq_a + 1] = b1;
            Asml[r_a + 64][2 * kq_a] = s0;  Asml[r_a + 64][2 * kq_a + 1] = s1;
        }
        if (tid < 128) {
            const float* e0 = &pb0.x;
            const float* e1 = &pb1.x;
#pragma unroll
            for (int j = 0; j < 4; j++) {
                u32 bg, sm;
                split2(e0[j], e1[j], bg, sm);   // lo = k even, hi = k odd
                Bbig[p_b][4 * nq_b + j] = bg;
                Bsml[p_b][4 * nq_b + j] = sm;
            }
        }
        __syncthreads();

        // prefetch next tile
        if (kt + 1 < KT) {
            int k0n = (kt + 1) * 16;
            pa0 = va0 ? *(const float4*)(A + (size_t)(row0 + r_a) * K + k0n + kq_a * 4)
                      : make_float4(0.f, 0.f, 0.f, 0.f);
            pa1 = va1 ? *(const float4*)(A + (size_t)(row0 + r_a + 64) * K + k0n + kq_a * 4)
                      : make_float4(0.f, 0.f, 0.f, 0.f);
            if (tid < 128) {
                pb0 = *(const float4*)(B + (size_t)(k0n + 2 * p_b) * N + col0 + nq_b * 4);
                pb1 = *(const float4*)(B + (size_t)(k0n + 2 * p_b + 1) * N + col0 + nq_b * 4);
            }
        }

        // fragments + mma (one K=16 step)
        u32 ab[2][4], as[2][4];
#pragma unroll
        for (int mt = 0; mt < 2; mt++) {
            int rb = rw + mt * 16;
            ab[mt][0] = Abig[rb + g][tig];       as[mt][0] = Asml[rb + g][tig];
            ab[mt][1] = Abig[rb + g + 8][tig];   as[mt][1] = Asml[rb + g + 8][tig];
            ab[mt][2] = Abig[rb + g][tig + 4];   as[mt][2] = Asml[rb + g][tig + 4];
            ab[mt][3] = Abig[rb + g + 8][tig + 4]; as[mt][3] = Asml[rb + g + 8][tig + 4];
        }
        u32 bb[4][2], bs[4][2];
#pragma unroll
        for (int nt = 0; nt < 4; nt++) {
            int cb = cw + nt * 8 + g;
            bb[nt][0] = Bbig[tig][cb];      bs[nt][0] = Bsml[tig][cb];
            bb[nt][1] = Bbig[tig + 4][cb];  bs[nt][1] = Bsml[tig + 4][cb];
        }
#pragma unroll
        for (int mt = 0; mt < 2; mt++)
#pragma unroll
            for (int nt = 0; nt < 4; nt++) {
                mma_bf16(acc[mt][nt], ab[mt], bb[nt]);
                mma_bf16(acc[mt][nt], ab[mt], bs[nt]);
                mma_bf16(acc[mt][nt], as[mt], bb[nt]);
            }
        __syncthreads();
    }

    // epilogue: bias add + store (dual store for CFG==0)
#pragma unroll
    for (int nt = 0; nt < 4; nt++) {
        int ccol = col0 + cw + nt * 8 + 2 * tig;
        float2 bbv = *(const float2*)&bias[ccol];
#pragma unroll
        for (int mt = 0; mt < 2; mt++) {
            int r1 = row0 + rw + mt * 16 + g;
            int r2 = r1 + 8;
            float2 o0 = make_float2(acc[mt][nt][0] + bbv.x, acc[mt][nt][1] + bbv.y);
            float2 o1 = make_float2(acc[mt][nt][2] + bbv.x, acc[mt][nt][3] + bbv.y);
            if (r1 < M) {
                *(float2*)(C + (size_t)r1 * N + ccol) = o0;
                if (CFG == 0) *(float2*)((float*)g_h0 + (size_t)r1 * N + ccol) = o0;
            }
            if (r2 < M) {
                *(float2*)(C + (size_t)r2 * N + ccol) = o1;
                if (CFG == 0) *(float2*)((float*)g_h0 + (size_t)r2 * N + ccol) = o1;
            }
        }
    }
}

// ---------------- pooling ----------------
#define STRIP 200
__global__ __launch_bounds__(256) void pool_kernel(
    const float* __restrict__ nr, const int* __restrict__ batch)
{
    int c = threadIdx.x;
    int n0 = blockIdx.x * STRIP;
    int n1 = min(n0 + STRIP, NN);
    if (n0 >= NN) return;
    int curg = clampi(batch[n0], 0, NG - 1);
    float acc = 0.f;
    int cnt_local = 0;
    for (int n = n0; n < n1; n++) {
        int g = clampi(batch[n], 0, NG - 1);
        if (g != curg) {
            atomicAdd(&g_sums[curg * OUTD + c], acc);
            if (c == 0) atomicAdd(&g_cnt[curg], (float)cnt_local);
            acc = 0.f; cnt_local = 0; curg = g;
        }
        acc += nr[(size_t)n * OUTD + c];
        cnt_local++;
    }
    atomicAdd(&g_sums[curg * OUTD + c], acc);
    if (c == 0) atomicAdd(&g_cnt[curg], (float)cnt_local);
}

__global__ void finalize_kernel(float* __restrict__ out) {
    int i = blockIdx.x * blockDim.x + threadIdx.x;
    if (i < NG * OUTD) out[i] = g_sums[i] / fmaxf(g_cnt[i >> 8], 1.0f);
}

// ---------------- launch ----------------
extern "C" void kernel_launch(void* const* d_in, const int* in_sizes, int n_in,
                              void* d_out, int out_size) {
    const float *x = 0, *W_in = 0, *b_in = 0, *alw = 0, *alb = 0,
                *arw = 0, *arb = 0, *W_out = 0, *b_out = 0;
    const int *ei = 0, *batch = 0;
    for (int i = 0; i < n_in; i++) {
        long long s = in_sizes[i];
        const void* p = d_in[i];
        switch (s) {
            case 25600000LL: x     = (const float*)p; break;
            case 1600000LL:  ei    = (const int*)p;   break;
            case 50000LL:    batch = (const int*)p;   break;
            case 131072LL:   W_in  = (const float*)p; break;
            case 65536LL:    W_out = (const float*)p; break;
            case 512LL:      if (!alw) alw = (const float*)p; else arw = (const float*)p; break;
            case 2LL:        if (!alb) alb = (const float*)p; else arb = (const float*)p; break;
            case 256LL:      if (!b_in) b_in = (const float*)p; else b_out = (const float*)p; break;
            default: break;
        }
    }
    float* out = (float*)d_out;

    const int T = 256;
    const int SB = (NN + 1023) / 1024;   // 49 scan blocks

    zeroi_kernel<<<(NN + T - 1) / T, T>>>();
    deg_kernel<<<(NE + T - 1) / T, T>>>(ei);
    dinv_kernel<<<(NN + T - 1) / T, T>>>();
    scanA_kernel<<<SB, 1024>>>();
    scanB_kernel<<<1, 64>>>(SB);
    scanC_kernel<<<SB, 1024>>>();
    fill_kernel<<<(NE + T - 1) / T, T>>>(ei);

    // input GEMM: g_h = g_h0 = x @ W_in + b_in
    dim3 g1((NN + 127) / 128, HIDD / 64);
    bfgemm_kernel<0><<<g1, 256>>>(x, W_in, b_in, nullptr, NN, IND, HIDD);

    // layer 0: g_h -> g_agg (relu fused)
    attn_kernel<<<(NN + 7) / 8, T>>>(0, alw, alb, arw, arb, 0);
    coef_kernel<<<(NE + T - 1) / T, T>>>(ei);
    gather_kernel<<<(NN + 3) / 4, 256>>>(0, 1);

    // layer 1: g_agg -> g_h (no relu)
    attn_kernel<<<(NN + 7) / 8, T>>>(1, alw, alb, arw, arb, 1);
    coef_kernel<<<(NE + T - 1) / T, T>>>(ei);
    gather_kernel<<<(NN + 3) / 4, 256>>>(1, 0);

    // output GEMM: node_repr = g_h @ W_out + b_out -> d_out
    dim3 g2((NN + 127) / 128, OUTD / 64);
    bfgemm_kernel<1><<<g2, 256>>>(nullptr, W_out, b_out, out, NN, HIDD, OUTD);

    // mean pool over sorted batch
    pool_kernel<<<(NN + STRIP - 1) / STRIP, 256>>>(out, batch);
    finalize_kernel<<<(NG * OUTD + T - 1) / T, T>>>(out + (size_t)NN * OUTD);
}